// round 10
// baseline (speedup 1.0000x reference)
#include <cuda_runtime.h>
#include <math.h>
#include <stdint.h>

// Problem constants
#define BB   4
#define CI   256
#define CO   256
#define HH   64
#define WWD  64
#define HWSZ (HH*WWD)
#define KKT  9
#define NCH  72            // K = 2304 in chunks of 32 channels (prep/conv granularity)
#define NCH64 36           // K = 2304 in chunks of 64 channels (main GEMM granularity)

// ---------------- scratch (device globals; no allocation) ----------------
__device__ float  g_xt[BB*HWSZ*CI];            // x in NHWC   (16.8 MB)
__device__ unsigned short g_Bh16[NCH*32*256];  // bf16 hi of dcn_w, [chunk][k32][n256]
__device__ unsigned short g_Bl16[NCH*32*256];  // bf16 lo
__device__ unsigned short g_oBh16[NCH*32*32];  // bf16 hi of offset_w, [chunk][k32][n32]
__device__ unsigned short g_oBl16[NCH*32*32];  // bf16 lo

// ---------------- helpers ----------------
__device__ __forceinline__ void cp16u(uint32_t dst, const void* src) {
    asm volatile("cp.async.cg.shared.global [%0], [%1], 16;\n" :: "r"(dst), "l"(src));
}
__device__ __forceinline__ void cp_commit() {
    asm volatile("cp.async.commit_group;\n" ::);
}
__device__ __forceinline__ void cp_wait0() {
    asm volatile("cp.async.wait_group 0;\n" ::: "memory");
}
__device__ __forceinline__ uint32_t smem_u32(const void* p) {
    uint32_t r;
    asm("{ .reg .u64 t; cvta.to.shared.u64 t, %1; cvt.u32.u64 %0, t; }" : "=r"(r) : "l"(p));
    return r;
}
// pack {lo, hi} floats to bf16x2 (round-to-nearest); lo in low 16 bits
__device__ __forceinline__ uint32_t bf16x2(float lo, float hi) {
    uint32_t r;
    asm("cvt.rn.bf16x2.f32 %0, %1, %2;" : "=r"(r) : "f"(hi), "f"(lo));
    return r;
}
__device__ __forceinline__ void ldm_x4(uint32_t* r, uint32_t addr) {
    asm volatile("ldmatrix.sync.aligned.m8n8.x4.shared.b16 {%0,%1,%2,%3}, [%4];"
        : "=r"(r[0]), "=r"(r[1]), "=r"(r[2]), "=r"(r[3]) : "r"(addr));
}
__device__ __forceinline__ void ldm_x4t(uint32_t* r, uint32_t addr) {
    asm volatile("ldmatrix.sync.aligned.m8n8.x4.trans.shared.b16 {%0,%1,%2,%3}, [%4];"
        : "=r"(r[0]), "=r"(r[1]), "=r"(r[2]), "=r"(r[3]) : "r"(addr));
}
__device__ __forceinline__ void mma_bf16(float* d, const uint32_t* a, const uint32_t* b) {
    asm volatile("mma.sync.aligned.m16n8k16.row.col.f32.bf16.bf16.f32 "
        "{%0,%1,%2,%3}, {%4,%5,%6,%7}, {%8,%9}, {%0,%1,%2,%3};"
        : "+f"(d[0]), "+f"(d[1]), "+f"(d[2]), "+f"(d[3])
        : "r"(a[0]), "r"(a[1]), "r"(a[2]), "r"(a[3]), "r"(b[0]), "r"(b[1]));
}
// split float4 -> hi/lo bf16x2 pairs
__device__ __forceinline__ void split4(float4 f, uint2& hh, uint2& ll) {
    uint32_t h01 = bf16x2(f.x, f.y), h23 = bf16x2(f.z, f.w);
    float hf0 = __uint_as_float(h01 << 16), hf1 = __uint_as_float(h01 & 0xffff0000u);
    float hf2 = __uint_as_float(h23 << 16), hf3 = __uint_as_float(h23 & 0xffff0000u);
    uint32_t l01 = bf16x2(f.x - hf0, f.y - hf1), l23 = bf16x2(f.z - hf2, f.w - hf3);
    hh = make_uint2(h01, h23);
    ll = make_uint2(l01, l23);
}

// ---------------- kernel 1: NCHW -> NHWC transpose of x ----------------
__global__ void k_transpose_x(const float* __restrict__ x) {
    __shared__ float tile[32][33];
    int b  = blockIdx.z;
    int c0 = blockIdx.y * 32;
    int p0 = blockIdx.x * 32;
    int tx = threadIdx.x, ty = threadIdx.y;   // 32 x 8
    #pragma unroll
    for (int j = 0; j < 32; j += 8)
        tile[ty + j][tx] = x[((b*CI + c0 + ty + j)*HWSZ) + p0 + tx];
    __syncthreads();
    #pragma unroll
    for (int j = 0; j < 32; j += 8)
        g_xt[(b*HWSZ + p0 + ty + j)*CI + c0 + tx] = tile[tx][ty + j];
}

// ---------------- kernel 2: dcn_w -> bf16 hi/lo chunk images [chunk][k32][n256] ------
__global__ void k_prep_b(const float* __restrict__ dw) {
    int idx = blockIdx.x * 256 + threadIdx.x;
    if (idx >= NCH*8192) return;
    int kc = idx >> 13;
    int r  = idx & 8191;
    int k  = r >> 8;
    int n  = r & 255;
    int tap = kc >> 3;
    int c   = (kc & 7)*32 + k;
    float v = dw[(n*CI + c)*KKT + tap];
    uint32_t hp = bf16x2(v, 0.0f);
    float hf = __uint_as_float(hp << 16);
    uint32_t lp = bf16x2(v - hf, 0.0f);
    g_Bh16[idx] = (unsigned short)(hp & 0xffff);
    g_Bl16[idx] = (unsigned short)(lp & 0xffff);
}

// ---------------- kernel 2b: offset_w -> bf16 hi/lo chunk images [chunk][k32][n32] ---
__global__ void k_prep_ob(const float* __restrict__ ow) {
    int idx = blockIdx.x * 256 + threadIdx.x;
    if (idx >= NCH*1024) return;
    int kc = idx >> 10;
    int r  = idx & 1023;
    int k  = r >> 5;
    int n  = r & 31;
    int tap = kc >> 3;
    int c   = (kc & 7)*32 + k;
    float v = (n < 27) ? ow[(n*CI + c)*KKT + tap] : 0.0f;
    uint32_t hp = bf16x2(v, 0.0f);
    float hf = __uint_as_float(hp << 16);
    uint32_t lp = bf16x2(v - hf, 0.0f);
    g_oBh16[idx] = (unsigned short)(hp & 0xffff);
    g_oBl16[idx] = (unsigned short)(lp & 0xffff);
}

// ---------------- fused kernel: M=128/block, grid 128; 64-ch main chunks -------------
// SMEM layout:
//   FA  : main A planes, 64 pix x 144B (64ch bf16 + 16B pad)   4 x 9216  = 36864
//   FB  : main B planes, 64 k x 528B                           4 x 33792 = 135168
//   CA  : conv A planes, 128 pix x 80B   (overlays FB)         4 x 10240
//   FBC : conv B planes, 32 k x 80B      (overlays FB)         4 x 2560
//   FSO : conv result float[128][33]     (overlays FA)
//   FPW/FPO: params, persist phase2 -> phase3
#define FA(s, f)   (((s)*2 + (f)) * 9216)
#define FB(s, f)   (36864 + ((s)*2 + (f)) * 33792)
#define CA(s, f)   (36864 + ((s)*2 + (f)) * 10240)
#define FBC(s, f)  (77824 + ((s)*2 + (f)) * 2560)
#define FSO        0
#define FPW        172032
#define FPO        190464
#define FSM_TOTAL  208896

__global__ __launch_bounds__(512, 1) void k_fused(float* __restrict__ out,
                                                  const float* __restrict__ ob) {
    extern __shared__ char sm[];
    uint32_t su = smem_u32(sm);

    int tid  = threadIdx.x;
    int lane = tid & 31;
    int wid  = tid >> 5;
    int b    = blockIdx.x >> 5;
    int hp   = blockIdx.x & 31;          // row pair: rows 2hp, 2hp+1
    int hw0  = hp * 128;
    const float* xb = g_xt + (size_t)b * HWSZ * CI;

    // common ldmatrix lane mapping
    int g  = lane >> 3, lr = lane & 7;
    int a_row = (g & 1)*8 + lr;
    int a_cb  = (g >> 1) * 16;
    int b_krow = (g & 1)*8 + lr;
    int b_cb  = (g >> 1) * 16;

    float4* spw = (float4*)(sm + FPW);
    int4*   spo = (int4*)  (sm + FPO);
    float (*so)[33] = (float(*)[33])(sm + FSO);

    // ======================= PHASE 1: offset conv (M=128, N=32) ====================
    {
        int mt = wid & 7;
        int npair = wid >> 3;

        int cgp = tid >> 2;
        int cgk = (tid & 3) * 8;
        int prow = cgp >> 6;
        int pcol = cgp & 63;

        int cbr = (tid & 127) >> 2;
        int cbs = (tid & 3) * 16;
        bool bld = (tid < 128);

        float accc[2][4];
        #pragma unroll
        for (int j = 0; j < 2; ++j)
            #pragma unroll
            for (int q = 0; q < 4; ++q) accc[j][q] = 0.0f;

        bool valid;
        const float* asrc;
        {
            int y = 2*hp + prow - 1, xx = pcol - 1;   // tap 0
            valid = (y >= 0) && (y < HH) && (xx >= 0) && (xx < WWD);
            asrc = g_xt + (((size_t)(b*HWSZ) + (size_t)(y*WWD + xx)) * CI) + cgk;
        }

        // prologue chunk 0
        {
            if (bld) {
                cp16u(su + FBC(0,0) + cbr*80 + cbs, (const char*)g_oBh16 + (size_t)cbr*64 + cbs);
                cp16u(su + FBC(1,0) + cbr*80 + cbs, (const char*)g_oBl16 + (size_t)cbr*64 + cbs);
            }
            cp_commit();
            #pragma unroll
            for (int q = 0; q < 2; ++q) {
                float4 f = valid ? *(const float4*)(asrc + q*4) : make_float4(0,0,0,0);
                uint2 hh, ll;
                split4(f, hh, ll);
                *(uint2*)(sm + CA(0,0) + cgp*80 + (cgk + q*4)*2) = hh;
                *(uint2*)(sm + CA(1,0) + cgp*80 + (cgk + q*4)*2) = ll;
            }
            cp_wait0();
        }
        __syncthreads();

        #pragma unroll 1
        for (int i = 0; i < NCH; ++i) {
            int buf = i & 1;

            float4 v[2];
            v[0] = make_float4(0,0,0,0); v[1] = v[0];
            if (i < NCH - 1) {
                int sn = i + 1;
                if ((sn & 7) == 0) {
                    int t = sn >> 3;
                    int y = 2*hp + prow + t/3 - 1, xx = pcol + t%3 - 1;
                    valid = (y >= 0) && (y < HH) && (xx >= 0) && (xx < WWD);
                    asrc = g_xt + (((size_t)(b*HWSZ) + (size_t)(y*WWD + xx)) * CI) + cgk;
                }
                if (valid) {
                    const float* p = asrc + (sn & 7)*32;
                    v[0] = *(const float4*)p;
                    v[1] = *(const float4*)(p + 4);
                }
                if (bld) {
                    const char* sbh = (const char*)g_oBh16 + ((size_t)sn*1024 + cbr*32)*2 + cbs;
                    const char* sbl = (const char*)g_oBl16 + ((size_t)sn*1024 + cbr*32)*2 + cbs;
                    cp16u(su + FBC(0, buf^1) + cbr*80 + cbs, sbh);
                    cp16u(su + FBC(1, buf^1) + cbr*80 + cbs, sbl);
                }
                cp_commit();
            }

            // conv MMA (2 k16 steps, 1 m16 x 2 n8, 3 splits)
            {
                uint32_t baseAh = su + CA(0, buf) + (mt*16 + a_row)*80 + a_cb;
                uint32_t baseAl = su + CA(1, buf) + (mt*16 + a_row)*80 + a_cb;
                uint32_t baseBh = su + FBC(0, buf) + b_krow*80 + npair*32 + b_cb;
                uint32_t baseBl = su + FBC(1, buf) + b_krow*80 + npair*32 + b_cb;
                #pragma unroll
                for (int ks = 0; ks < 2; ++ks) {
                    uint32_t aH[4], aL[4];
                    ldm_x4(aH, baseAh + ks*32);
                    ldm_x4(aL, baseAl + ks*32);
                    uint32_t bH[2][2], bL[2][2], t4[4];
                    ldm_x4t(t4, baseBh + ks*1280);
                    bH[0][0]=t4[0]; bH[0][1]=t4[1]; bH[1][0]=t4[2]; bH[1][1]=t4[3];
                    ldm_x4t(t4, baseBl + ks*1280);
                    bL[0][0]=t4[0]; bL[0][1]=t4[1]; bL[1][0]=t4[2]; bL[1][1]=t4[3];
                    #pragma unroll
                    for (int nt = 0; nt < 2; ++nt) {
                        mma_bf16(accc[nt], aH, bH[nt]);
                        mma_bf16(accc[nt], aH, bL[nt]);
                        mma_bf16(accc[nt], aL, bH[nt]);
                    }
                }
            }

            if (i < NCH - 1) {
                int nb = buf ^ 1;
                #pragma unroll
                for (int q = 0; q < 2; ++q) {
                    uint2 hh, ll;
                    split4(v[q], hh, ll);
                    *(uint2*)(sm + CA(0, nb) + cgp*80 + (cgk + q*4)*2) = hh;
                    *(uint2*)(sm + CA(1, nb) + cgp*80 + (cgk + q*4)*2) = ll;
                }
                cp_wait0();
            }
            __syncthreads();
        }

        // scatter conv result
        {
            int r0 = mt*16 + (lane >> 2);
            int c0 = npair*16 + (lane & 3)*2;
            #pragma unroll
            for (int nt = 0; nt < 2; ++nt) {
                int c = c0 + nt*8;
                so[r0][c]       = accc[nt][0];
                so[r0][c+1]     = accc[nt][1];
                so[r0 + 8][c]   = accc[nt][2];
                so[r0 + 8][c+1] = accc[nt][3];
            }
        }
        __syncthreads();
    }

    // ======================= PHASE 2: param build (128 pixels) =====================
    if (tid < 128) {
        float ov[27];
        #pragma unroll
        for (int oc = 0; oc < 27; ++oc) ov[oc] = so[tid][oc] + ob[oc];

        int w    = tid & 63;
        int hloc = 2*hp + (tid >> 6);
        #pragma unroll
        for (int kk = 0; kk < 9; ++kk) {
            float dy = ov[2*kk];
            float dx = ov[2*kk + 1];
            float m  = 1.0f / (1.0f + expf(-ov[18 + kk]));
            int ki = kk / 3, kj = kk % 3;
            float py = (float)(hloc - 1 + ki) + dy;
            float px = (float)(w - 1 + kj) + dx;
            float fy = floorf(py), fx = floorf(px);
            float wy = py - fy,    wx = px - fx;
            int y0 = (int)fy, x0 = (int)fx;
            int y1 = y0 + 1,  x1 = x0 + 1;

            bool vy0 = (y0 >= 0) && (y0 < HH);
            bool vy1 = (y1 >= 0) && (y1 < HH);
            bool vx0 = (x0 >= 0) && (x0 < WWD);
            bool vx1 = (x1 >= 0) && (x1 < WWD);

            float w00 = (1.0f - wy) * (1.0f - wx) * m * ((vy0 && vx0) ? 1.0f : 0.0f);
            float w01 = (1.0f - wy) * wx          * m * ((vy0 && vx1) ? 1.0f : 0.0f);
            float w10 = wy * (1.0f - wx)          * m * ((vy1 && vx0) ? 1.0f : 0.0f);
            float w11 = wy * wx                   * m * ((vy1 && vx1) ? 1.0f : 0.0f);

            int yc0 = min(max(y0, 0), HH - 1);
            int yc1 = min(max(y1, 0), HH - 1);
            int xc0 = min(max(x0, 0), WWD - 1);
            int xc1 = min(max(x1, 0), WWD - 1);

            spw[kk*128 + tid] = make_float4(w00, w01, w10, w11);
            spo[kk*128 + tid] = make_int4((yc0*WWD + xc0)*CI, (yc0*WWD + xc1)*CI,
                                          (yc1*WWD + xc0)*CI, (yc1*WWD + xc1)*CI);
        }
    }
    __syncthreads();

    // ======================= PHASE 3: main GEMM, 64-ch chunks, two 64-pixel passes ==
    int mh = (wid & 1) * 32;
    int ns = (wid >> 1) * 32;
    int gp = tid >> 3;
    int gk = (tid & 7) * 4;
    int br  = tid >> 3;           // B-load k row (0..63)
    int bsg = (tid & 7) * 64;     // byte segment (64B per thread per split)

// MMA over k16 steps ks0, ks0+1 of the 64-ch chunk in `buf`
#define MMA2(ks0) do { \
    uint32_t baseAh = su + FA(0, buf) + (mh + a_row)*144 + a_cb; \
    uint32_t baseAl = su + FA(1, buf) + (mh + a_row)*144 + a_cb; \
    uint32_t baseBh = su + FB(0, buf) + b_krow*528 + ns*2 + b_cb; \
    uint32_t baseBl = su + FB(1, buf) + b_krow*528 + ns*2 + b_cb; \
    _Pragma("unroll") \
    for (int ks = (ks0); ks < (ks0) + 2; ++ks) { \
        uint32_t aH[2][4], aL[2][4]; \
        ldm_x4(aH[0], baseAh + ks*32); \
        ldm_x4(aH[1], baseAh + 2304 + ks*32); \
        ldm_x4(aL[0], baseAl + ks*32); \
        ldm_x4(aL[1], baseAl + 2304 + ks*32); \
        uint32_t bH[4][2], bL[4][2], t4[4]; \
        ldm_x4t(t4, baseBh + ks*8448); \
        bH[0][0]=t4[0]; bH[0][1]=t4[1]; bH[1][0]=t4[2]; bH[1][1]=t4[3]; \
        ldm_x4t(t4, baseBh + ks*8448 + 32); \
        bH[2][0]=t4[0]; bH[2][1]=t4[1]; bH[3][0]=t4[2]; bH[3][1]=t4[3]; \
        ldm_x4t(t4, baseBl + ks*8448); \
        bL[0][0]=t4[0]; bL[0][1]=t4[1]; bL[1][0]=t4[2]; bL[1][1]=t4[3]; \
        ldm_x4t(t4, baseBl + ks*8448 + 32); \
        bL[2][0]=t4[0]; bL[2][1]=t4[1]; bL[3][0]=t4[2]; bL[3][1]=t4[3]; \
        _Pragma("unroll") \
        for (int mt = 0; mt < 2; ++mt) \
            _Pragma("unroll") \
            for (int nt = 0; nt < 4; ++nt) { \
                mma_bf16(acc[mt][nt], aH[mt], bH[nt]); \
                mma_bf16(acc[mt][nt], aH[mt], bL[nt]); \
                mma_bf16(acc[mt][nt], aL[mt], bH[nt]); \
            } \
    } } while (0)

#define GATHER4(basep) do { \
    v0 = *(const float4*)((basep) + po.x); \
    v1 = *(const float4*)((basep) + po.y); \
    v2 = *(const float4*)((basep) + po.z); \
    v3 = *(const float4*)((basep) + po.w); \
} while (0)

#define BLENDSTORE(bufw, choff) do { \
    float4 s; \
    s.x = wv.x*v0.x + wv.y*v1.x + wv.z*v2.x + wv.w*v3.x; \
    s.y = wv.x*v0.y + wv.y*v1.y + wv.z*v2.y + wv.w*v3.y; \
    s.z = wv.x*v0.z + wv.y*v1.z + wv.z*v2.z + wv.w*v3.z; \
    s.w = wv.x*v0.w + wv.y*v1.w + wv.z*v2.w + wv.w*v3.w; \
    uint2 hh, ll; \
    split4(s, hh, ll); \
    *(uint2*)(sm + FA(0, bufw) + gp*144 + ((choff) + gk)*2) = hh; \
    *(uint2*)(sm + FA(1, bufw) + gp*144 + ((choff) + gk)*2) = ll; \
} while (0)

    #pragma unroll 1
    for (int pass = 0; pass < 2; ++pass) {
        int pb = pass * 64;

        float acc[2][4][4];
        #pragma unroll
        for (int i = 0; i < 2; ++i)
            #pragma unroll
            for (int j = 0; j < 4; ++j)
                #pragma unroll
                for (int q = 0; q < 4; ++q) acc[i][j][q] = 0.0f;

        // prologue: build 64-ch chunk 0 into buf 0
        {
            int4   po = spo[pb + gp];
            float4 wv = spw[pb + gp];
            // B(0): rows 0..63 (chunks 0,1 contiguous in global)
            const char* srcb = (const char*)g_Bh16 + (size_t)br*512 + bsg;
            const char* srcl = (const char*)g_Bl16 + (size_t)br*512 + bsg;
            uint32_t dstb = su + FB(0,0) + br*528 + bsg;
            uint32_t dstl = su + FB(1,0) + br*528 + bsg;
            #pragma unroll
            for (int q = 0; q < 4; ++q) {
                cp16u(dstb + q*16, srcb + q*16);
                cp16u(dstl + q*16, srcl + q*16);
            }
            cp_commit();
            float4 v0, v1, v2, v3;
            const float* base0 = xb + gk;
            GATHER4(base0);
            { int buf = 0; (void)buf; }
            BLENDSTORE(0, 0);
            GATHER4(base0 + 32);
            BLENDSTORE(0, 32);
            cp_wait0();
        }
        __syncthreads();

        #pragma unroll 1
        for (int i = 0; i < NCH64; ++i) {
            int buf = i & 1;

            int4   po;
            float4 wv;
            const float* base0 = 0;
            if (i < NCH64 - 1) {
                int sn = i + 1;
                int t = sn >> 2;
                po = spo[t*128 + pb + gp];
                wv = spw[t*128 + pb + gp];
                base0 = xb + (sn & 3)*64 + gk;
                const char* srcb = (const char*)g_Bh16 + (size_t)sn*32768 + br*512 + bsg;
                const char* srcl = (const char*)g_Bl16 + (size_t)sn*32768 + br*512 + bsg;
                uint32_t dstb = su + FB(0, buf^1) + br*528 + bsg;
                uint32_t dstl = su + FB(1, buf^1) + br*528 + bsg;
                #pragma unroll
                for (int q = 0; q < 4; ++q) {
                    cp16u(dstb + q*16, srcb + q*16);
                    cp16u(dstl + q*16, srcl + q*16);
                }
                cp_commit();
            }

            float4 v0, v1, v2, v3;
            if (i < NCH64 - 1) GATHER4(base0);

            MMA2(0);

            if (i < NCH64 - 1) {
                BLENDSTORE(buf^1, 0);
                GATHER4(base0 + 32);
            }

            MMA2(2);

            if (i < NCH64 - 1) {
                BLENDSTORE(buf^1, 32);
                cp_wait0();
            }
            __syncthreads();
        }

        // epilogue
        {
            float* op = out + ((size_t)(b*CO))*HWSZ + hw0 + pb;
            int r0 = mh + (lane >> 2);
            int c0 = ns + (lane & 3)*2;
            #pragma unroll
            for (int mt = 0; mt < 2; ++mt) {
                int r = r0 + mt*16;
                #pragma unroll
                for (int nt = 0; nt < 4; ++nt) {
                    int c = c0 + nt*8;
                    op[(size_t)c*HWSZ + r]           = acc[mt][nt][0];
                    op[(size_t)(c+1)*HWSZ + r]       = acc[mt][nt][1];
                    op[(size_t)c*HWSZ + r + 8]       = acc[mt][nt][2];
                    op[(size_t)(c+1)*HWSZ + r + 8]   = acc[mt][nt][3];
                }
            }
        }
        __syncthreads();
    }
}

// ---------------- launch ----------------
extern "C" void kernel_launch(void* const* d_in, const int* in_sizes, int n_in,
                              void* d_out, int out_size) {
    (void)in_sizes; (void)n_in; (void)out_size;
    const float* x  = (const float*)d_in[0];   // (4,256,64,64)
    const float* ow = (const float*)d_in[1];   // (27,256,3,3)
    const float* ob = (const float*)d_in[2];   // (27,)
    const float* dw = (const float*)d_in[3];   // (256,256,3,3)
    float* out = (float*)d_out;                // (4,256,64,64)

    cudaFuncSetAttribute(k_fused, cudaFuncAttributeMaxDynamicSharedMemorySize, FSM_TOTAL);

    dim3 tb(32, 8);
    dim3 tg(HWSZ/32, CI/32, BB);
    k_transpose_x<<<tg, tb>>>(x);
    k_prep_b<<<(NCH*8192 + 255)/256, 256>>>(dw);
    k_prep_ob<<<(NCH*1024 + 255)/256, 256>>>(ow);
    k_fused<<<128, 512, FSM_TOTAL>>>(out, ob);
}

// round 11
// speedup vs baseline: 1.0192x; 1.0192x over previous
#include <cuda_runtime.h>
#include <math.h>
#include <stdint.h>

// Problem constants
#define BB   4
#define CI   256
#define CO   256
#define HH   64
#define WWD  64
#define HWSZ (HH*WWD)
#define KKT  9
#define NCH  72            // K = 2304 in chunks of 32 channels

// ---------------- scratch (device globals; no allocation) ----------------
__device__ float  g_xt[BB*HWSZ*CI];            // x in NHWC   (16.8 MB)
__device__ unsigned short g_Bh16[NCH*32*256];  // bf16 hi of dcn_w, [chunk][k32][n256]
__device__ unsigned short g_Bl16[NCH*32*256];  // bf16 lo
__device__ unsigned short g_oBh16[NCH*32*32];  // bf16 hi of offset_w, [chunk][k32][n32]
__device__ unsigned short g_oBl16[NCH*32*32];  // bf16 lo
__device__ float4 g_pw[BB*KKT*HWSZ];           // premasked bilinear weights
__device__ int4   g_po[BB*KKT*HWSZ];           // clamped corner element offsets

// ---------------- helpers ----------------
__device__ __forceinline__ void cp16u(uint32_t dst, const void* src) {
    asm volatile("cp.async.cg.shared.global [%0], [%1], 16;\n" :: "r"(dst), "l"(src));
}
__device__ __forceinline__ void cp_commit() {
    asm volatile("cp.async.commit_group;\n" ::);
}
__device__ __forceinline__ void cp_wait0() {
    asm volatile("cp.async.wait_group 0;\n" ::: "memory");
}
__device__ __forceinline__ uint32_t smem_u32(const void* p) {
    uint32_t r;
    asm("{ .reg .u64 t; cvta.to.shared.u64 t, %1; cvt.u32.u64 %0, t; }" : "=r"(r) : "l"(p));
    return r;
}
// pack {lo, hi} floats to bf16x2 (round-to-nearest); lo in low 16 bits
__device__ __forceinline__ uint32_t bf16x2(float lo, float hi) {
    uint32_t r;
    asm("cvt.rn.bf16x2.f32 %0, %1, %2;" : "=r"(r) : "f"(hi), "f"(lo));
    return r;
}
__device__ __forceinline__ void ldm_x4(uint32_t* r, uint32_t addr) {
    asm volatile("ldmatrix.sync.aligned.m8n8.x4.shared.b16 {%0,%1,%2,%3}, [%4];"
        : "=r"(r[0]), "=r"(r[1]), "=r"(r[2]), "=r"(r[3]) : "r"(addr));
}
__device__ __forceinline__ void ldm_x4t(uint32_t* r, uint32_t addr) {
    asm volatile("ldmatrix.sync.aligned.m8n8.x4.trans.shared.b16 {%0,%1,%2,%3}, [%4];"
        : "=r"(r[0]), "=r"(r[1]), "=r"(r[2]), "=r"(r[3]) : "r"(addr));
}
__device__ __forceinline__ void mma_bf16(float* d, const uint32_t* a, const uint32_t* b) {
    asm volatile("mma.sync.aligned.m16n8k16.row.col.f32.bf16.bf16.f32 "
        "{%0,%1,%2,%3}, {%4,%5,%6,%7}, {%8,%9}, {%0,%1,%2,%3};"
        : "+f"(d[0]), "+f"(d[1]), "+f"(d[2]), "+f"(d[3])
        : "r"(a[0]), "r"(a[1]), "r"(a[2]), "r"(a[3]), "r"(b[0]), "r"(b[1]));
}
// split float4 -> hi/lo bf16x2 pairs
__device__ __forceinline__ void split4(float4 f, uint2& hh, uint2& ll) {
    uint32_t h01 = bf16x2(f.x, f.y), h23 = bf16x2(f.z, f.w);
    float hf0 = __uint_as_float(h01 << 16), hf1 = __uint_as_float(h01 & 0xffff0000u);
    float hf2 = __uint_as_float(h23 << 16), hf3 = __uint_as_float(h23 & 0xffff0000u);
    uint32_t l01 = bf16x2(f.x - hf0, f.y - hf1), l23 = bf16x2(f.z - hf2, f.w - hf3);
    hh = make_uint2(h01, h23);
    ll = make_uint2(l01, l23);
}

// ---------------- kernel 1: NCHW -> NHWC transpose of x ----------------
__global__ void k_transpose_x(const float* __restrict__ x) {
    __shared__ float tile[32][33];
    int b  = blockIdx.z;
    int c0 = blockIdx.y * 32;
    int p0 = blockIdx.x * 32;
    int tx = threadIdx.x, ty = threadIdx.y;   // 32 x 8
    #pragma unroll
    for (int j = 0; j < 32; j += 8)
        tile[ty + j][tx] = x[((b*CI + c0 + ty + j)*HWSZ) + p0 + tx];
    __syncthreads();
    #pragma unroll
    for (int j = 0; j < 32; j += 8)
        g_xt[(b*HWSZ + p0 + ty + j)*CI + c0 + tx] = tile[tx][ty + j];
}

// ---------------- kernel 2: dcn_w -> bf16 hi/lo chunk images [chunk][k32][n256] ------
__global__ void k_prep_b(const float* __restrict__ dw) {
    int idx = blockIdx.x * 256 + threadIdx.x;
    if (idx >= NCH*8192) return;
    int kc = idx >> 13;
    int r  = idx & 8191;
    int k  = r >> 8;
    int n  = r & 255;
    int tap = kc >> 3;
    int c   = (kc & 7)*32 + k;
    float v = dw[(n*CI + c)*KKT + tap];
    uint32_t hp = bf16x2(v, 0.0f);
    float hf = __uint_as_float(hp << 16);
    uint32_t lp = bf16x2(v - hf, 0.0f);
    g_Bh16[idx] = (unsigned short)(hp & 0xffff);
    g_Bl16[idx] = (unsigned short)(lp & 0xffff);
}

// ---------------- kernel 2b: offset_w -> bf16 hi/lo chunk images [chunk][k32][n32] ---
__global__ void k_prep_ob(const float* __restrict__ ow) {
    int idx = blockIdx.x * 256 + threadIdx.x;
    if (idx >= NCH*1024) return;
    int kc = idx >> 10;
    int r  = idx & 1023;
    int k  = r >> 5;
    int n  = r & 31;
    int tap = kc >> 3;
    int c   = (kc & 7)*32 + k;
    float v = (n < 27) ? ow[(n*CI + c)*KKT + tap] : 0.0f;
    uint32_t hp = bf16x2(v, 0.0f);
    float hf = __uint_as_float(hp << 16);
    uint32_t lp = bf16x2(v - hf, 0.0f);
    g_oBh16[idx] = (unsigned short)(hp & 0xffff);
    g_oBl16[idx] = (unsigned short)(lp & 0xffff);
}

// ---------------- kernel 3: offset conv via bf16x3 mma.sync + param build ------------
// (round-7 version, measured 59.8us) grid 256 = (b,h). 128 threads.
#define OOF_A(s, f)  (((s)*2 + (f)) * 5120)
#define OOF_B(s, f)  (20480 + ((s)*2 + (f)) * 2560)
#define OOF_SO       30720
#define OSM_TOTAL    39168

__global__ __launch_bounds__(128) void k_offset(const float* __restrict__ ob) {
    __shared__ __align__(16) char sm[OSM_TOTAL];
    uint32_t su = smem_u32(sm);
    float (*so)[33] = (float(*)[33])(sm + OOF_SO);

    int tid  = threadIdx.x;
    int lane = tid & 31;
    int wrp  = tid >> 5;
    int b    = blockIdx.x >> 6;
    int h    = blockIdx.x & 63;

    int g  = lane >> 3, lr = lane & 7;
    int a_row  = (g & 1)*8 + lr;
    int a_cb   = (g >> 1) * 16;
    int b_krow = (g & 1)*8 + lr;
    int b_cb   = (g >> 1) * 16;

    int gp = tid >> 1;
    int gk = (tid & 1) * 16;
    int br = tid >> 2;
    int bc = (tid & 3) * 8;

    float acc[4][4];
    #pragma unroll
    for (int j = 0; j < 4; ++j)
        #pragma unroll
        for (int q = 0; q < 4; ++q) acc[j][q] = 0.0f;

    bool valid;
    const float* asrc;
    {
        int y = h - 1, xx = gp - 1;
        valid = (y >= 0) && (xx >= 0) && (xx < WWD);
        asrc = g_xt + (((size_t)(b*HWSZ) + (size_t)(y*WWD + xx)) * CI) + gk;
    }

    {
        const char* srcb = (const char*)g_oBh16 + (size_t)br*64 + bc*2;
        const char* srcl = (const char*)g_oBl16 + (size_t)br*64 + bc*2;
        cp16u(su + OOF_B(0,0) + br*80 + bc*2, srcb);
        cp16u(su + OOF_B(1,0) + br*80 + bc*2, srcl);
        cp_commit();
        #pragma unroll
        for (int q = 0; q < 4; ++q) {
            float4 f = make_float4(0,0,0,0);
            if (valid) f = *(const float4*)(asrc + q*4);
            uint2 hh, ll;
            split4(f, hh, ll);
            *(uint2*)(sm + OOF_A(0,0) + gp*80 + (gk + q*4)*2) = hh;
            *(uint2*)(sm + OOF_A(1,0) + gp*80 + (gk + q*4)*2) = ll;
        }
        cp_wait0();
    }
    __syncthreads();

    #pragma unroll 1
    for (int i = 0; i < NCH; ++i) {
        int buf = i & 1;

        float4 v[4];
        if (i < NCH - 1) {
            int sn = i + 1;
            if ((sn & 7) == 0) {
                int t = sn >> 3;
                int y = h + t/3 - 1, xx = gp + t%3 - 1;
                valid = (y >= 0) && (y < HH) && (xx >= 0) && (xx < WWD);
                asrc = g_xt + (((size_t)(b*HWSZ) + (size_t)(y*WWD + xx)) * CI) + gk;
            }
            const float* p = asrc + (sn & 7)*32;
            #pragma unroll
            for (int q = 0; q < 4; ++q)
                v[q] = valid ? *(const float4*)(p + q*4) : make_float4(0,0,0,0);
            const char* srcb = (const char*)g_oBh16 + ((size_t)sn*1024 + br*32)*2 + bc*2;
            const char* srcl = (const char*)g_oBl16 + ((size_t)sn*1024 + br*32)*2 + bc*2;
            cp16u(su + OOF_B(0, buf^1) + br*80 + bc*2, srcb);
            cp16u(su + OOF_B(1, buf^1) + br*80 + bc*2, srcl);
            cp_commit();
        }

        uint32_t baseAh = su + OOF_A(0, buf) + (wrp*16 + a_row)*80 + a_cb;
        uint32_t baseAl = su + OOF_A(1, buf) + (wrp*16 + a_row)*80 + a_cb;
        uint32_t baseBh = su + OOF_B(0, buf) + b_krow*80 + b_cb;
        uint32_t baseBl = su + OOF_B(1, buf) + b_krow*80 + b_cb;
        #pragma unroll
        for (int ks = 0; ks < 2; ++ks) {
            uint32_t aH[4], aL[4];
            ldm_x4(aH, baseAh + ks*32);
            ldm_x4(aL, baseAl + ks*32);
            uint32_t bH[4][2], bL[4][2], t4[4];
            ldm_x4t(t4, baseBh + ks*1280);
            bH[0][0]=t4[0]; bH[0][1]=t4[1]; bH[1][0]=t4[2]; bH[1][1]=t4[3];
            ldm_x4t(t4, baseBh + ks*1280 + 32);
            bH[2][0]=t4[0]; bH[2][1]=t4[1]; bH[3][0]=t4[2]; bH[3][1]=t4[3];
            ldm_x4t(t4, baseBl + ks*1280);
            bL[0][0]=t4[0]; bL[0][1]=t4[1]; bL[1][0]=t4[2]; bL[1][1]=t4[3];
            ldm_x4t(t4, baseBl + ks*1280 + 32);
            bL[2][0]=t4[0]; bL[2][1]=t4[1]; bL[3][0]=t4[2]; bL[3][1]=t4[3];
            #pragma unroll
            for (int nt = 0; nt < 4; ++nt) {
                mma_bf16(acc[nt], aH, bH[nt]);
                mma_bf16(acc[nt], aH, bL[nt]);
                mma_bf16(acc[nt], aL, bH[nt]);
            }
        }

        if (i < NCH - 1) {
            int nb = buf ^ 1;
            #pragma unroll
            for (int q = 0; q < 4; ++q) {
                uint2 hh, ll;
                split4(v[q], hh, ll);
                *(uint2*)(sm + OOF_A(0, nb) + gp*80 + (gk + q*4)*2) = hh;
                *(uint2*)(sm + OOF_A(1, nb) + gp*80 + (gk + q*4)*2) = ll;
            }
            cp_wait0();
        }
        __syncthreads();
    }

    {
        int r0 = wrp*16 + (lane >> 2);
        int c0 = (lane & 3)*2;
        #pragma unroll
        for (int nt = 0; nt < 4; ++nt) {
            int c = c0 + nt*8;
            so[r0][c]       = acc[nt][0];
            so[r0][c+1]     = acc[nt][1];
            so[r0 + 8][c]   = acc[nt][2];
            so[r0 + 8][c+1] = acc[nt][3];
        }
    }
    __syncthreads();

    if (tid < 64) {
        float ov[27];
        #pragma unroll
        for (int oc = 0; oc < 27; ++oc) ov[oc] = so[tid][oc] + ob[oc];

        int w  = tid;
        int hw = h * WWD + w;
        #pragma unroll
        for (int kk = 0; kk < 9; ++kk) {
            float dy = ov[2*kk];
            float dx = ov[2*kk + 1];
            float m  = 1.0f / (1.0f + expf(-ov[18 + kk]));
            int ki = kk / 3, kj = kk % 3;
            float py = (float)(h - 1 + ki) + dy;
            float px = (float)(w - 1 + kj) + dx;
            float fy = floorf(py), fx = floorf(px);
            float wy = py - fy,    wx = px - fx;
            int y0 = (int)fy, x0 = (int)fx;
            int y1 = y0 + 1,  x1 = x0 + 1;

            bool vy0 = (y0 >= 0) && (y0 < HH);
            bool vy1 = (y1 >= 0) && (y1 < HH);
            bool vx0 = (x0 >= 0) && (x0 < WWD);
            bool vx1 = (x1 >= 0) && (x1 < WWD);

            float w00 = (1.0f - wy) * (1.0f - wx) * m * ((vy0 && vx0) ? 1.0f : 0.0f);
            float w01 = (1.0f - wy) * wx          * m * ((vy0 && vx1) ? 1.0f : 0.0f);
            float w10 = wy * (1.0f - wx)          * m * ((vy1 && vx0) ? 1.0f : 0.0f);
            float w11 = wy * wx                   * m * ((vy1 && vx1) ? 1.0f : 0.0f);

            int yc0 = min(max(y0, 0), HH - 1);
            int yc1 = min(max(y1, 0), HH - 1);
            int xc0 = min(max(x0, 0), WWD - 1);
            int xc1 = min(max(x1, 0), WWD - 1);

            int idx = ((b*KKT + kk)*HWSZ) + hw;
            g_pw[idx] = make_float4(w00, w01, w10, w11);
            g_po[idx] = make_int4((yc0*WWD + xc0)*CI, (yc0*WWD + xc1)*CI,
                                  (yc1*WWD + xc0)*CI, (yc1*WWD + xc1)*CI);
        }
    }
}

// ---------------- kernel 4: main GEMM, 2 CTAs/SM ----------------
// grid 512 = (b, h, n-half), 256 threads (8 warps). M=64 pix, N=128, 32-ch chunks.
// SMEM: A planes 64x80B x4 = 20480; B planes 32x272B x4 = 34816; params 4096.
#define MA(s, f)   (((s)*2 + (f)) * 5120)
#define MB(s, f)   (20480 + ((s)*2 + (f)) * 8704)
#define MPW        55296
#define MPO        57344
#define MSM_TOTAL  59392

__global__ __launch_bounds__(256, 2) void k_main(float* __restrict__ out) {
    extern __shared__ char sm[];
    uint32_t su = smem_u32(sm);

    int tid  = threadIdx.x;
    int lane = tid & 31;
    int wid  = tid >> 5;
    int b    = blockIdx.x >> 7;
    int h    = (blockIdx.x >> 1) & 63;
    int nh   = blockIdx.x & 1;
    int hw0  = h * WWD;
    const float* xb = g_xt + (size_t)b * HWSZ * CI;

    // ldmatrix lane mapping
    int g  = lane >> 3, lr = lane & 7;
    int a_row = (g & 1)*8 + lr;
    int a_cb  = (g >> 1) * 16;
    int b_krow = (g & 1)*8 + lr;
    int b_cb  = (g >> 1) * 16;

    int mh = (wid & 1) * 32;          // pixel half
    int ns = (wid >> 1) * 32;         // n slice within the 128-half

    // A-build: 64 pix x 32 ch / 256 thr -> 8 ch per thread, two 4-ch sub-steps
    int gp = tid >> 2;
    int gk = (tid & 3) * 8;
    // B-load: 2 splits x 32 rows x 256B / 256 thr -> 32B per split
    int br  = tid >> 3;
    int bsg = (tid & 7) * 32;

    float4* pwp = (float4*)(sm + MPW);
    int4*   pop = (int4*)  (sm + MPO);

    float acc[2][4][4];
    #pragma unroll
    for (int i = 0; i < 2; ++i)
        #pragma unroll
        for (int j = 0; j < 4; ++j)
            #pragma unroll
            for (int q = 0; q < 4; ++q) acc[i][j][q] = 0.0f;

    // preload params for taps 0 and 1
    if (tid < 128) {
        int t = tid >> 6;
        int pp = tid & 63;
        int pidx = ((b*KKT + t)*HWSZ) + hw0 + pp;
        pwp[t*64 + pp] = g_pw[pidx];
        pop[t*64 + pp] = g_po[pidx];
    }
    __syncthreads();

#define GATH(basep, off) do { \
    v0 = *(const float4*)((basep) + po.x + (off)); \
    v1 = *(const float4*)((basep) + po.y + (off)); \
    v2 = *(const float4*)((basep) + po.z + (off)); \
    v3 = *(const float4*)((basep) + po.w + (off)); \
} while (0)

#define BSTORE(bufw, choff) do { \
    float4 s; \
    s.x = wv.x*v0.x + wv.y*v1.x + wv.z*v2.x + wv.w*v3.x; \
    s.y = wv.x*v0.y + wv.y*v1.y + wv.z*v2.y + wv.w*v3.y; \
    s.z = wv.x*v0.z + wv.y*v1.z + wv.z*v2.z + wv.w*v3.z; \
    s.w = wv.x*v0.w + wv.y*v1.w + wv.z*v2.w + wv.w*v3.w; \
    uint2 hh, ll; \
    split4(s, hh, ll); \
    *(uint2*)(sm + MA(0, bufw) + gp*80 + (choff)*2) = hh; \
    *(uint2*)(sm + MA(1, bufw) + gp*80 + (choff)*2) = ll; \
} while (0)

#define MMA1(ks) do { \
    uint32_t baseAh = su + MA(0, buf) + (mh + a_row)*80 + a_cb; \
    uint32_t baseAl = su + MA(1, buf) + (mh + a_row)*80 + a_cb; \
    uint32_t baseBh = su + MB(0, buf) + b_krow*272 + ns*2 + b_cb; \
    uint32_t baseBl = su + MB(1, buf) + b_krow*272 + ns*2 + b_cb; \
    uint32_t aH[2][4], aL[2][4]; \
    ldm_x4(aH[0], baseAh + (ks)*32); \
    ldm_x4(aH[1], baseAh + 1280 + (ks)*32); \
    ldm_x4(aL[0], baseAl + (ks)*32); \
    ldm_x4(aL[1], baseAl + 1280 + (ks)*32); \
    uint32_t bH[4][2], bL[4][2], t4[4]; \
    ldm_x4t(t4, baseBh + (ks)*4352); \
    bH[0][0]=t4[0]; bH[0][1]=t4[1]; bH[1][0]=t4[2]; bH[1][1]=t4[3]; \
    ldm_x4t(t4, baseBh + (ks)*4352 + 32); \
    bH[2][0]=t4[0]; bH[2][1]=t4[1]; bH[3][0]=t4[2]; bH[3][1]=t4[3]; \
    ldm_x4t(t4, baseBl + (ks)*4352); \
    bL[0][0]=t4[0]; bL[0][1]=t4[1]; bL[1][0]=t4[2]; bL[1][1]=t4[3]; \
    ldm_x4t(t4, baseBl + (ks)*4352 + 32); \
    bL[2][0]=t4[0]; bL[2][1]=t4[1]; bL[3][0]=t4[2]; bL[3][1]=t4[3]; \
    _Pragma("unroll") \
    for (int mt = 0; mt < 2; ++mt) \
        _Pragma("unroll") \
        for (int nt = 0; nt < 4; ++nt) { \
            mma_bf16(acc[mt][nt], aH[mt], bH[nt]); \
            mma_bf16(acc[mt][nt], aH[mt], bL[nt]); \
            mma_bf16(acc[mt][nt], aL[mt], bH[nt]); \
        } \
} while (0)

#define LOADB(sn, bufw) do { \
    const char* srcb = (const char*)g_Bh16 + ((size_t)(sn)*8192 + br*256)*2 + nh*256 + bsg; \
    const char* srcl = (const char*)g_Bl16 + ((size_t)(sn)*8192 + br*256)*2 + nh*256 + bsg; \
    uint32_t dstb = su + MB(0, bufw) + br*272 + bsg; \
    uint32_t dstl = su + MB(1, bufw) + br*272 + bsg; \
    cp16u(dstb, srcb); cp16u(dstb + 16, srcb + 16); \
    cp16u(dstl, srcl); cp16u(dstl + 16, srcl + 16); \
    cp_commit(); \
} while (0)

    // prologue: build chunk 0 into buf 0
    {
        float4 wv = pwp[gp];
        int4   po = pop[gp];
        float4 v0, v1, v2, v3;
        LOADB(0, 0);
        const float* base0 = xb + gk;
        GATH(base0, 0);
        BSTORE(0, gk);
        GATH(base0, 4);
        BSTORE(0, gk + 4);
        cp_wait0();
    }
    __syncthreads();

    #pragma unroll 1
    for (int i = 0; i < NCH; ++i) {
        int buf = i & 1;

        // param ring prefetch
        if ((i & 7) == 0 && i >= 8 && i <= 56 && tid < 64) {
            int t = (i >> 3) + 1;
            int slot = t & 1;
            int pidx = ((b*KKT + t)*HWSZ) + hw0 + tid;
            pwp[slot*64 + tid] = g_pw[pidx];
            pop[slot*64 + tid] = g_po[pidx];
        }

        int4   po;
        float4 wv;
        const float* base0 = 0;
        float4 v0, v1, v2, v3;
        if (i < NCH - 1) {
            int sn = i + 1;
            int slot = (sn >> 3) & 1;
            po = pop[slot*64 + gp];
            wv = pwp[slot*64 + gp];
            base0 = xb + (sn & 7)*32 + gk;
            LOADB(sn, buf^1);
            GATH(base0, 0);
        }

        MMA1(0);

        if (i < NCH - 1) {
            BSTORE(buf^1, gk);
            GATH(base0, 4);
        }

        MMA1(1);

        if (i < NCH - 1) {
            BSTORE(buf^1, gk + 4);
            cp_wait0();
        }
        __syncthreads();
    }

    // epilogue: out[b][n][h][w], n = nh*128 + ns + ...
    {
        float* op = out + ((size_t)(b*CO))*HWSZ + hw0;
        int r0 = mh + (lane >> 2);
        int c0 = nh*128 + ns + (lane & 3)*2;
        #pragma unroll
        for (int mt = 0; mt < 2; ++mt) {
            int r = r0 + mt*16;
            #pragma unroll
            for (int nt = 0; nt < 4; ++nt) {
                int c = c0 + nt*8;
                op[(size_t)c*HWSZ + r]           = acc[mt][nt][0];
                op[(size_t)(c+1)*HWSZ + r]       = acc[mt][nt][1];
                op[(size_t)c*HWSZ + r + 8]       = acc[mt][nt][2];
                op[(size_t)(c+1)*HWSZ + r + 8]   = acc[mt][nt][3];
            }
        }
    }
}

// ---------------- launch ----------------
extern "C" void kernel_launch(void* const* d_in, const int* in_sizes, int n_in,
                              void* d_out, int out_size) {
    (void)in_sizes; (void)n_in; (void)out_size;
    const float* x  = (const float*)d_in[0];   // (4,256,64,64)
    const float* ow = (const float*)d_in[1];   // (27,256,3,3)
    const float* ob = (const float*)d_in[2];   // (27,)
    const float* dw = (const float*)d_in[3];   // (256,256,3,3)
    float* out = (float*)d_out;                // (4,256,64,64)

    cudaFuncSetAttribute(k_main, cudaFuncAttributeMaxDynamicSharedMemorySize, MSM_TOTAL);

    dim3 tb(32, 8);
    dim3 tg(HWSZ/32, CI/32, BB);
    k_transpose_x<<<tg, tb>>>(x);
    k_prep_b<<<(NCH*8192 + 255)/256, 256>>>(dw);
    k_prep_ob<<<(NCH*1024 + 255)/256, 256>>>(ow);
    k_offset<<<256, 128>>>(ob);
    k_main<<<512, 256, MSM_TOTAL>>>(out);
}

// round 12
// speedup vs baseline: 1.0325x; 1.0131x over previous
#include <cuda_runtime.h>
#include <math.h>
#include <stdint.h>

// Problem constants
#define BB   4
#define CI   256
#define CO   256
#define HH   64
#define WWD  64
#define HWSZ (HH*WWD)
#define KKT  9
#define NCH  72            // K = 2304 in chunks of 32 channels

// ---------------- scratch (device globals; no allocation) ----------------
__device__ float  g_xt[BB*HWSZ*CI];            // x in NHWC   (16.8 MB)
__device__ unsigned short g_Bh16[NCH*32*256];  // bf16 hi of dcn_w, [chunk][k32][n256]
__device__ unsigned short g_Bl16[NCH*32*256];  // bf16 lo
__device__ unsigned short g_oBh16[NCH*32*32];  // bf16 hi of offset_w, [chunk][k32][n32]
__device__ unsigned short g_oBl16[NCH*32*32];  // bf16 lo

// ---------------- helpers ----------------
__device__ __forceinline__ void cp16u(uint32_t dst, const void* src) {
    asm volatile("cp.async.cg.shared.global [%0], [%1], 16;\n" :: "r"(dst), "l"(src));
}
__device__ __forceinline__ void cp_commit() {
    asm volatile("cp.async.commit_group;\n" ::);
}
__device__ __forceinline__ void cp_wait0() {
    asm volatile("cp.async.wait_group 0;\n" ::: "memory");
}
__device__ __forceinline__ uint32_t smem_u32(const void* p) {
    uint32_t r;
    asm("{ .reg .u64 t; cvta.to.shared.u64 t, %1; cvt.u32.u64 %0, t; }" : "=r"(r) : "l"(p));
    return r;
}
__device__ __forceinline__ uint32_t bf16x2(float lo, float hi) {
    uint32_t r;
    asm("cvt.rn.bf16x2.f32 %0, %1, %2;" : "=r"(r) : "f"(hi), "f"(lo));
    return r;
}
__device__ __forceinline__ void ldm_x4(uint32_t* r, uint32_t addr) {
    asm volatile("ldmatrix.sync.aligned.m8n8.x4.shared.b16 {%0,%1,%2,%3}, [%4];"
        : "=r"(r[0]), "=r"(r[1]), "=r"(r[2]), "=r"(r[3]) : "r"(addr));
}
__device__ __forceinline__ void ldm_x4t(uint32_t* r, uint32_t addr) {
    asm volatile("ldmatrix.sync.aligned.m8n8.x4.trans.shared.b16 {%0,%1,%2,%3}, [%4];"
        : "=r"(r[0]), "=r"(r[1]), "=r"(r[2]), "=r"(r[3]) : "r"(addr));
}
__device__ __forceinline__ void mma_bf16(float* d, const uint32_t* a, const uint32_t* b) {
    asm volatile("mma.sync.aligned.m16n8k16.row.col.f32.bf16.bf16.f32 "
        "{%0,%1,%2,%3}, {%4,%5,%6,%7}, {%8,%9}, {%0,%1,%2,%3};"
        : "+f"(d[0]), "+f"(d[1]), "+f"(d[2]), "+f"(d[3])
        : "r"(a[0]), "r"(a[1]), "r"(a[2]), "r"(a[3]), "r"(b[0]), "r"(b[1]));
}
__device__ __forceinline__ void split4(float4 f, uint2& hh, uint2& ll) {
    uint32_t h01 = bf16x2(f.x, f.y), h23 = bf16x2(f.z, f.w);
    float hf0 = __uint_as_float(h01 << 16), hf1 = __uint_as_float(h01 & 0xffff0000u);
    float hf2 = __uint_as_float(h23 << 16), hf3 = __uint_as_float(h23 & 0xffff0000u);
    uint32_t l01 = bf16x2(f.x - hf0, f.y - hf1), l23 = bf16x2(f.z - hf2, f.w - hf3);
    hh = make_uint2(h01, h23);
    ll = make_uint2(l01, l23);
}
#define BAR_SYNC(id)   asm volatile("bar.sync %0, 512;"   :: "r"(id) : "memory")
#define BAR_ARRIVE(id) asm volatile("bar.arrive %0, 512;" :: "r"(id) : "memory")

// ---------------- kernel 1: NCHW -> NHWC transpose of x ----------------
__global__ void k_transpose_x(const float* __restrict__ x) {
    __shared__ float tile[32][33];
    int b  = blockIdx.z;
    int c0 = blockIdx.y * 32;
    int p0 = blockIdx.x * 32;
    int tx = threadIdx.x, ty = threadIdx.y;   // 32 x 8
    #pragma unroll
    for (int j = 0; j < 32; j += 8)
        tile[ty + j][tx] = x[((b*CI + c0 + ty + j)*HWSZ) + p0 + tx];
    __syncthreads();
    #pragma unroll
    for (int j = 0; j < 32; j += 8)
        g_xt[(b*HWSZ + p0 + ty + j)*CI + c0 + tx] = tile[tx][ty + j];
}

// ---------------- kernel 2: dcn_w -> bf16 hi/lo chunk images ----------------
__global__ void k_prep_b(const float* __restrict__ dw) {
    int idx = blockIdx.x * 256 + threadIdx.x;
    if (idx >= NCH*8192) return;
    int kc = idx >> 13;
    int r  = idx & 8191;
    int k  = r >> 8;
    int n  = r & 255;
    int tap = kc >> 3;
    int c   = (kc & 7)*32 + k;
    float v = dw[(n*CI + c)*KKT + tap];
    uint32_t hp = bf16x2(v, 0.0f);
    float hf = __uint_as_float(hp << 16);
    uint32_t lp = bf16x2(v - hf, 0.0f);
    g_Bh16[idx] = (unsigned short)(hp & 0xffff);
    g_Bl16[idx] = (unsigned short)(lp & 0xffff);
}

// ---------------- kernel 2b: offset_w -> bf16 hi/lo chunk images ----------------
__global__ void k_prep_ob(const float* __restrict__ ow) {
    int idx = blockIdx.x * 256 + threadIdx.x;
    if (idx >= NCH*1024) return;
    int kc = idx >> 10;
    int r  = idx & 1023;
    int k  = r >> 5;
    int n  = r & 31;
    int tap = kc >> 3;
    int c   = (kc & 7)*32 + k;
    float v = (n < 27) ? ow[(n*CI + c)*KKT + tap] : 0.0f;
    uint32_t hp = bf16x2(v, 0.0f);
    float hf = __uint_as_float(hp << 16);
    uint32_t lp = bf16x2(v - hf, 0.0f);
    g_oBh16[idx] = (unsigned short)(hp & 0xffff);
    g_oBl16[idx] = (unsigned short)(lp & 0xffff);
}

// ---------------- fused kernel: conv + params + warp-specialized main GEMM ----------
// grid 256 = (b,h), 512 threads. M=64 pix, N=256, K=2304, 32-ch chunks.
// Main phase: warps 8-15 produce A/B into a 3-stage ring; warps 0-7 consume (MMA).
// Stage layout (stride 44032): A planes 2 x (64 x 80B), B planes 2 x (32 x 528B).
#define SA(st, s)  ((st)*44032 + (s)*5120)
#define SB(st, s)  ((st)*44032 + 10240 + (s)*16896)
// conv-phase overlays (inside stage region, dead before main phase)
#define CFA(s, f)  (((s)*2 + (f)) * 5120)
#define CFB(s, f)  (20480 + ((s)*2 + (f)) * 2560)
#define CSO        30720
// params (persist)
#define SPW        132096
#define SPO        141312
#define FSM_TOTAL  150528

__global__ __launch_bounds__(512, 1) void k_fused(float* __restrict__ out,
                                                  const float* __restrict__ ob) {
    extern __shared__ char sm[];
    uint32_t su = smem_u32(sm);

    int tid  = threadIdx.x;
    int lane = tid & 31;
    int wid  = tid >> 5;
    int b    = blockIdx.x >> 6;
    int h    = blockIdx.x & 63;
    int hw0  = h * WWD;
    const float* xb = g_xt + (size_t)b * HWSZ * CI;

    // common ldmatrix lane mapping
    int g  = lane >> 3, lr = lane & 7;
    int a_row = (g & 1)*8 + lr;
    int a_cb  = (g >> 1) * 16;
    int b_krow = (g & 1)*8 + lr;
    int b_cb  = (g >> 1) * 16;

    float4* spw = (float4*)(sm + SPW);
    int4*   spo = (int4*)  (sm + SPO);
    float (*so)[33] = (float(*)[33])(sm + CSO);

    // ======================= PHASE 1: offset conv (M=64, N=32) =====================
    {
        int mt = wid & 3;
        int npair = (wid >> 2) & 1;
        bool mma_act = (wid < 8);

        int cbr = (tid & 127) >> 2;
        int cbs = (tid & 3) * 16;
        bool bld = (tid < 128);

        int gp = tid >> 3;
        int gk = (tid & 7) * 4;

        float accc[2][4];
        #pragma unroll
        for (int j = 0; j < 2; ++j)
            #pragma unroll
            for (int q = 0; q < 4; ++q) accc[j][q] = 0.0f;

        bool valid;
        const float* asrc;
        {
            int y = h - 1, xx = gp - 1;   // tap 0
            valid = (y >= 0) && (y < HH) && (xx >= 0) && (xx < WWD);
            asrc = g_xt + (((size_t)(b*HWSZ) + (size_t)(y*WWD + xx)) * CI) + gk;
        }

        {
            if (bld) {
                cp16u(su + CFB(0,0) + cbr*80 + cbs, (const char*)g_oBh16 + (size_t)cbr*64 + cbs);
                cp16u(su + CFB(1,0) + cbr*80 + cbs, (const char*)g_oBl16 + (size_t)cbr*64 + cbs);
            }
            cp_commit();
            float4 f = valid ? *(const float4*)asrc : make_float4(0,0,0,0);
            uint2 hh, ll;
            split4(f, hh, ll);
            *(uint2*)(sm + CFA(0,0) + gp*80 + gk*2) = hh;
            *(uint2*)(sm + CFA(1,0) + gp*80 + gk*2) = ll;
            cp_wait0();
        }
        __syncthreads();

        #pragma unroll 1
        for (int i = 0; i < NCH; ++i) {
            int buf = i & 1;

            float4 v = make_float4(0,0,0,0);
            if (i < NCH - 1) {
                int sn = i + 1;
                if ((sn & 7) == 0) {
                    int t = sn >> 3;
                    int y = h + t/3 - 1, xx = gp + t%3 - 1;
                    valid = (y >= 0) && (y < HH) && (xx >= 0) && (xx < WWD);
                    asrc = g_xt + (((size_t)(b*HWSZ) + (size_t)(y*WWD + xx)) * CI) + gk;
                }
                if (valid) v = *(const float4*)(asrc + (sn & 7)*32);
                if (bld) {
                    const char* sbh = (const char*)g_oBh16 + ((size_t)sn*1024 + cbr*32)*2 + cbs;
                    const char* sbl = (const char*)g_oBl16 + ((size_t)sn*1024 + cbr*32)*2 + cbs;
                    cp16u(su + CFB(0, buf^1) + cbr*80 + cbs, sbh);
                    cp16u(su + CFB(1, buf^1) + cbr*80 + cbs, sbl);
                }
                cp_commit();
            }

            if (mma_act) {
                uint32_t baseAh = su + CFA(0, buf) + (mt*16 + a_row)*80 + a_cb;
                uint32_t baseAl = su + CFA(1, buf) + (mt*16 + a_row)*80 + a_cb;
                uint32_t baseBh = su + CFB(0, buf) + b_krow*80 + npair*32 + b_cb;
                uint32_t baseBl = su + CFB(1, buf) + b_krow*80 + npair*32 + b_cb;
                #pragma unroll
                for (int ks = 0; ks < 2; ++ks) {
                    uint32_t aH[4], aL[4];
                    ldm_x4(aH, baseAh + ks*32);
                    ldm_x4(aL, baseAl + ks*32);
                    uint32_t bH[2][2], bL[2][2], t4[4];
                    ldm_x4t(t4, baseBh + ks*1280);
                    bH[0][0]=t4[0]; bH[0][1]=t4[1]; bH[1][0]=t4[2]; bH[1][1]=t4[3];
                    ldm_x4t(t4, baseBl + ks*1280);
                    bL[0][0]=t4[0]; bL[0][1]=t4[1]; bL[1][0]=t4[2]; bL[1][1]=t4[3];
                    #pragma unroll
                    for (int nt = 0; nt < 2; ++nt) {
                        mma_bf16(accc[nt], aH, bH[nt]);
                        mma_bf16(accc[nt], aH, bL[nt]);
                        mma_bf16(accc[nt], aL, bH[nt]);
                    }
                }
            }

            if (i < NCH - 1) {
                int nb = buf ^ 1;
                uint2 hh, ll;
                split4(v, hh, ll);
                *(uint2*)(sm + CFA(0, nb) + gp*80 + gk*2) = hh;
                *(uint2*)(sm + CFA(1, nb) + gp*80 + gk*2) = ll;
                cp_wait0();
            }
            __syncthreads();
        }

        if (mma_act) {
            int r0 = mt*16 + (lane >> 2);
            int c0 = npair*16 + (lane & 3)*2;
            #pragma unroll
            for (int nt = 0; nt < 2; ++nt) {
                int c = c0 + nt*8;
                so[r0][c]       = accc[nt][0];
                so[r0][c+1]     = accc[nt][1];
                so[r0 + 8][c]   = accc[nt][2];
                so[r0 + 8][c+1] = accc[nt][3];
            }
        }
        __syncthreads();
    }

    // ======================= PHASE 2: param build (all 9 taps) =====================
    if (tid < 64) {
        float ov[27];
        #pragma unroll
        for (int oc = 0; oc < 27; ++oc) ov[oc] = so[tid][oc] + ob[oc];

        int w = tid;
        #pragma unroll
        for (int kk = 0; kk < 9; ++kk) {
            float dy = ov[2*kk];
            float dx = ov[2*kk + 1];
            float m  = 1.0f / (1.0f + expf(-ov[18 + kk]));
            int ki = kk / 3, kj = kk % 3;
            float py = (float)(h - 1 + ki) + dy;
            float px = (float)(w - 1 + kj) + dx;
            float fy = floorf(py), fx = floorf(px);
            float wy = py - fy,    wx = px - fx;
            int y0 = (int)fy, x0 = (int)fx;
            int y1 = y0 + 1,  x1 = x0 + 1;

            bool vy0 = (y0 >= 0) && (y0 < HH);
            bool vy1 = (y1 >= 0) && (y1 < HH);
            bool vx0 = (x0 >= 0) && (x0 < WWD);
            bool vx1 = (x1 >= 0) && (x1 < WWD);

            float w00 = (1.0f - wy) * (1.0f - wx) * m * ((vy0 && vx0) ? 1.0f : 0.0f);
            float w01 = (1.0f - wy) * wx          * m * ((vy0 && vx1) ? 1.0f : 0.0f);
            float w10 = wy * (1.0f - wx)          * m * ((vy1 && vx0) ? 1.0f : 0.0f);
            float w11 = wy * wx                   * m * ((vy1 && vx1) ? 1.0f : 0.0f);

            int yc0 = min(max(y0, 0), HH - 1);
            int yc1 = min(max(y1, 0), HH - 1);
            int xc0 = min(max(x0, 0), WWD - 1);
            int xc1 = min(max(x1, 0), WWD - 1);

            spw[kk*64 + w] = make_float4(w00, w01, w10, w11);
            spo[kk*64 + w] = make_int4((yc0*WWD + xc0)*CI, (yc0*WWD + xc1)*CI,
                                       (yc1*WWD + xc0)*CI, (yc1*WWD + xc1)*CI);
        }
    }
    __syncthreads();

    // ======================= PHASE 3: warp-specialized main GEMM ===================
    if (wid >= 8) {
        // ---- PRODUCERS ----
        int ptid = tid - 256;
        int gp  = ptid >> 2;           // pixel 0..63
        int gk  = (ptid & 3) * 8;      // 8 channels per thread
        int br  = ptid >> 3;           // B k row 0..31
        int bsg = (ptid & 7) * 64;     // 64B per split

        #pragma unroll 1
        for (int i = 0; i < NCH; ++i) {
            int st = i - (i/3)*3;
            if (i >= 3) BAR_SYNC(4 + st);

            int t = i >> 3;
            int4   po = spo[t*64 + gp];
            float4 wv = spw[t*64 + gp];

            // B via cp.async
            const char* srcb = (const char*)g_Bh16 + ((size_t)i*8192 + br*256)*2 + bsg;
            const char* srcl = (const char*)g_Bl16 + ((size_t)i*8192 + br*256)*2 + bsg;
            uint32_t dstb = su + SB(st,0) + br*528 + bsg;
            uint32_t dstl = su + SB(st,1) + br*528 + bsg;
            #pragma unroll
            for (int q = 0; q < 4; ++q) {
                cp16u(dstb + q*16, srcb + q*16);
                cp16u(dstl + q*16, srcl + q*16);
            }
            cp_commit();

            // A gather + blend + split, two 4-ch substeps
            const float* base0 = xb + (i & 7)*32 + gk;
            #pragma unroll
            for (int sub = 0; sub < 2; ++sub) {
                int off = sub * 4;
                float4 v0 = *(const float4*)(base0 + po.x + off);
                float4 v1 = *(const float4*)(base0 + po.y + off);
                float4 v2 = *(const float4*)(base0 + po.z + off);
                float4 v3 = *(const float4*)(base0 + po.w + off);
                float4 s;
                s.x = wv.x*v0.x + wv.y*v1.x + wv.z*v2.x + wv.w*v3.x;
                s.y = wv.x*v0.y + wv.y*v1.y + wv.z*v2.y + wv.w*v3.y;
                s.z = wv.x*v0.z + wv.y*v1.z + wv.z*v2.z + wv.w*v3.z;
                s.w = wv.x*v0.w + wv.y*v1.w + wv.z*v2.w + wv.w*v3.w;
                uint2 hh, ll;
                split4(s, hh, ll);
                *(uint2*)(sm + SA(st,0) + gp*80 + (gk + off)*2) = hh;
                *(uint2*)(sm + SA(st,1) + gp*80 + (gk + off)*2) = ll;
            }
            cp_wait0();
            BAR_ARRIVE(1 + st);
        }
    } else {
        // ---- CONSUMERS ----
        int mh = (wid & 1) * 32;
        int ns = (wid >> 1) * 64;

        float acc[2][8][4];
        #pragma unroll
        for (int i = 0; i < 2; ++i)
            #pragma unroll
            for (int j = 0; j < 8; ++j)
                #pragma unroll
                for (int q = 0; q < 4; ++q) acc[i][j][q] = 0.0f;

        #pragma unroll 1
        for (int i = 0; i < NCH; ++i) {
            int st = i - (i/3)*3;
            BAR_SYNC(1 + st);

            uint32_t Ah = su + SA(st,0) + (mh + a_row)*80 + a_cb;
            uint32_t Al = su + SA(st,1) + (mh + a_row)*80 + a_cb;
            uint32_t Bh = su + SB(st,0) + b_krow*528 + ns*2 + b_cb;
            uint32_t Bl = su + SB(st,1) + b_krow*528 + ns*2 + b_cb;

            #pragma unroll
            for (int ks = 0; ks < 2; ++ks) {
                uint32_t aH[2][4], aL[2][4];
                ldm_x4(aH[0], Ah + ks*32);
                ldm_x4(aH[1], Ah + 1280 + ks*32);
                ldm_x4(aL[0], Al + ks*32);
                ldm_x4(aL[1], Al + 1280 + ks*32);
                #pragma unroll
                for (int nh2 = 0; nh2 < 2; ++nh2) {
                    uint32_t bH[4][2], bL[4][2], t4[4];
                    ldm_x4t(t4, Bh + ks*8448 + nh2*64);
                    bH[0][0]=t4[0]; bH[0][1]=t4[1]; bH[1][0]=t4[2]; bH[1][1]=t4[3];
                    ldm_x4t(t4, Bh + ks*8448 + nh2*64 + 32);
                    bH[2][0]=t4[0]; bH[2][1]=t4[1]; bH[3][0]=t4[2]; bH[3][1]=t4[3];
                    ldm_x4t(t4, Bl + ks*8448 + nh2*64);
                    bL[0][0]=t4[0]; bL[0][1]=t4[1]; bL[1][0]=t4[2]; bL[1][1]=t4[3];
                    ldm_x4t(t4, Bl + ks*8448 + nh2*64 + 32);
                    bL[2][0]=t4[0]; bL[2][1]=t4[1]; bL[3][0]=t4[2]; bL[3][1]=t4[3];
                    #pragma unroll
                    for (int mt = 0; mt < 2; ++mt)
                        #pragma unroll
                        for (int nt = 0; nt < 4; ++nt) {
                            float* a4 = acc[mt][nh2*4 + nt];
                            mma_bf16(a4, aH[mt], bH[nt]);
                            mma_bf16(a4, aH[mt], bL[nt]);
                            mma_bf16(a4, aL[mt], bH[nt]);
                        }
                }
            }
            BAR_ARRIVE(4 + st);
        }

        // epilogue: out[b][n][h][w]
        float* op = out + ((size_t)(b*CO))*HWSZ + hw0;
        int r0 = mh + (lane >> 2);
        int c0 = ns + (lane & 3)*2;
        #pragma unroll
        for (int mt = 0; mt < 2; ++mt) {
            int r = r0 + mt*16;
            #pragma unroll
            for (int j = 0; j < 8; ++j) {
                int c = c0 + j*8;
                op[(size_t)c*HWSZ + r]           = acc[mt][j][0];
                op[(size_t)(c+1)*HWSZ + r]       = acc[mt][j][1];
                op[(size_t)c*HWSZ + r + 8]       = acc[mt][j][2];
                op[(size_t)(c+1)*HWSZ + r + 8]   = acc[mt][j][3];
            }
        }
    }
}

// ---------------- launch ----------------
extern "C" void kernel_launch(void* const* d_in, const int* in_sizes, int n_in,
                              void* d_out, int out_size) {
    (void)in_sizes; (void)n_in; (void)out_size;
    const float* x  = (const float*)d_in[0];   // (4,256,64,64)
    const float* ow = (const float*)d_in[1];   // (27,256,3,3)
    const float* ob = (const float*)d_in[2];   // (27,)
    const float* dw = (const float*)d_in[3];   // (256,256,3,3)
    float* out = (float*)d_out;                // (4,256,64,64)

    cudaFuncSetAttribute(k_fused, cudaFuncAttributeMaxDynamicSharedMemorySize, FSM_TOTAL);

    dim3 tb(32, 8);
    dim3 tg(HWSZ/32, CI/32, BB);
    k_transpose_x<<<tg, tb>>>(x);
    k_prep_b<<<(NCH*8192 + 255)/256, 256>>>(dw);
    k_prep_ob<<<(NCH*1024 + 255)/256, 256>>>(ow);
    k_fused<<<256, 512, FSM_TOTAL>>>(out, ob);
}